// round 14
// baseline (speedup 1.0000x reference)
#include <cuda_runtime.h>
#include <math.h>

// ---------------- problem constants ----------------
#define BB      32
#define HH      56
#define CCH     192
#define WS      7
#define SSHIFT  3
#define NHEAD   6
#define HD      32
#define NN      49                  // WS*WS
#define NWIMG   64                  // (56/7)^2
#define NWIN    (BB*NWIMG)          // 2048
#define NTOK    (BB*HH*HH)          // 100352
#define FFDIM   768                 // 4*C
#define QK_SCALE 0.1767766952966369f  // 32^-0.5

// ---------------- scratch (device globals; no allocs allowed) ----------------
__device__ float g_hwin[(size_t)NTOK * CCH];
__device__ float g_q[(size_t)NTOK * CCH];
__device__ float g_k[(size_t)NTOK * CCH];
__device__ float g_v[(size_t)NTOK * CCH];
__device__ float g_attnout[(size_t)NTOK * CCH];
__device__ float g_x1[(size_t)NTOK * CCH];
__device__ float g_ln2[(size_t)NTOK * CCH];
__device__ float g_fc1[(size_t)NTOK * FFDIM];

// ---------------- LayerNorm (warp per token), optional shift+window scatter ----
// PERM==1: write LN(x) into window-partitioned, cyclically-shifted layout
//   dst row = (b*64 + wh*8 + ww)*49 + r*7 + c  where (wh*7+r) = (h-3) mod 56 etc.
template <int PERM>
__global__ void ln_kernel(const float* __restrict__ x,
                          const float* __restrict__ g,
                          const float* __restrict__ b,
                          float* __restrict__ out)
{
    const int warp = threadIdx.x >> 5;
    const int lane = threadIdx.x & 31;
    const int tok  = blockIdx.x * 8 + warp;   // grid = NTOK/8 exactly

    const float* px = x + (size_t)tok * CCH;
    float v[6];
    float s = 0.f, sq = 0.f;
#pragma unroll
    for (int t = 0; t < 6; t++) {
        float a = px[lane + 32 * t];
        v[t] = a; s += a; sq += a * a;
    }
#pragma unroll
    for (int o = 16; o > 0; o >>= 1) {
        s  += __shfl_xor_sync(0xffffffffu, s,  o);
        sq += __shfl_xor_sync(0xffffffffu, sq, o);
    }
    const float mu  = s * (1.0f / CCH);
    const float var = sq * (1.0f / CCH) - mu * mu;
    const float inv = rsqrtf(var + 1e-5f);

    size_t drow;
    if (PERM) {
        const int bb = tok / (HH * HH);
        const int hw = tok - bb * (HH * HH);
        const int h  = hw / HH, w = hw - (hw / HH) * HH;
        int ph = h - SSHIFT; if (ph < 0) ph += HH;
        int pw = w - SSHIFT; if (pw < 0) pw += HH;
        const int wh = ph / WS, r = ph - wh * WS;
        const int ww = pw / WS, c = pw - ww * WS;
        drow = (size_t)((bb * NWIMG + wh * 8 + ww) * NN + r * WS + c);
    } else {
        drow = (size_t)tok;
    }
    float* po = out + drow * CCH;
#pragma unroll
    for (int t = 0; t < 6; t++) {
        const int ch = lane + 32 * t;
        po[ch] = (v[t] - mu) * inv * g[ch] + b[ch];
    }
}

// ---------------- SGEMM 128x128x16, 256 thr, 8x8/thread, fused epilogues ------
// A: (M,K) row-major.  B: (K,N) row-major.  M%128==0, K%16==0; N guarded.
// EPI 0: qkv split/scale   -> C0=q (pre-scaled), C1=k, C2=v   (win,head,n,hd)
// EPI 1: proj + residual, window-reverse+unshift scatter       -> C0=x1 (+addsrc=x)
// EPI 2: bias + exact GELU                                     -> C0=fc1out
// EPI 3: bias + residual add                                   -> C0=out (+addsrc=x1)
template <int EPI>
__global__ __launch_bounds__(256)
void gemm_k(const float* __restrict__ A, const float* __restrict__ B,
            const float* __restrict__ bias, const float* __restrict__ addsrc,
            float* __restrict__ C0, float* __restrict__ C1, float* __restrict__ C2,
            int M, int N, int K)
{
    __shared__ float As[16][128];
    __shared__ float Bs[16][128];

    const int tid = threadIdx.x;
    const int bm  = blockIdx.y * 128;
    const int bn  = blockIdx.x * 128;
    const int tx  = tid & 15;
    const int ty  = tid >> 4;

    float acc[8][8];
#pragma unroll
    for (int i = 0; i < 8; i++)
#pragma unroll
        for (int j = 0; j < 8; j++) acc[i][j] = 0.f;

    for (int k0 = 0; k0 < K; k0 += 16) {
        // load A tile (128x16), store transposed As[k][m]
#pragma unroll
        for (int i = 0; i < 2; i++) {
            const int idx = tid * 2 + i;
            const int ar = idx >> 2;
            const int ac = (idx & 3) << 2;
            const float4 va = *(const float4*)(A + (size_t)(bm + ar) * K + k0 + ac);
            As[ac + 0][ar] = va.x;
            As[ac + 1][ar] = va.y;
            As[ac + 2][ar] = va.z;
            As[ac + 3][ar] = va.w;
        }
        // load B tile (16x128), guarded in N
#pragma unroll
        for (int i = 0; i < 2; i++) {
            const int idx = tid * 2 + i;
            const int br = idx >> 5;
            const int bc = (idx & 31) << 2;
            float4 vb = make_float4(0.f, 0.f, 0.f, 0.f);
            if (bn + bc < N)
                vb = *(const float4*)(B + (size_t)(k0 + br) * N + bn + bc);
            *(float4*)&Bs[br][bc] = vb;
        }
        __syncthreads();

#pragma unroll
        for (int kk = 0; kk < 16; kk++) {
            float ra[8], rb[8];
            *(float4*)&ra[0] = *(const float4*)&As[kk][ty * 8];
            *(float4*)&ra[4] = *(const float4*)&As[kk][ty * 8 + 4];
            *(float4*)&rb[0] = *(const float4*)&Bs[kk][tx * 8];
            *(float4*)&rb[4] = *(const float4*)&Bs[kk][tx * 8 + 4];
#pragma unroll
            for (int i = 0; i < 8; i++)
#pragma unroll
                for (int j = 0; j < 8; j++)
                    acc[i][j] += ra[i] * rb[j];
        }
        __syncthreads();
    }

    // ---------------- epilogue ----------------
#pragma unroll
    for (int i = 0; i < 8; i++) {
        const int row = bm + ty * 8 + i;

        if (EPI == 0) {
            const int win = row / NN;
            const int n   = row - win * NN;
#pragma unroll
            for (int j = 0; j < 8; j++) {
                const int col = bn + tx * 8 + j;
                if (col < N) {
                    float val = acc[i][j] + bias[col];
                    const int part = col / CCH;
                    const int rem  = col - part * CCH;
                    const int head = rem >> 5;
                    const int d    = rem & 31;
                    if (part == 0) val *= QK_SCALE;
                    float* dst = (part == 0) ? C0 : (part == 1) ? C1 : C2;
                    dst[(size_t)((win * NHEAD + head) * NN + n) * HD + d] = val;
                }
            }
        } else if (EPI == 1) {
            const int win = row / NN;
            const int n   = row - win * NN;
            const int bb  = win >> 6;
            const int wl  = win & 63;
            const int wh  = wl >> 3, ww = wl & 7;
            const int r   = n / 7,   c  = n - (n / 7) * 7;
            int h = wh * 7 + r + SSHIFT; if (h >= HH) h -= HH;
            int w = ww * 7 + c + SSHIFT; if (w >= HH) w -= HH;
            const size_t tok = (size_t)bb * (HH * HH) + h * HH + w;
#pragma unroll
            for (int j = 0; j < 8; j++) {
                const int col = bn + tx * 8 + j;
                if (col < N)
                    C0[tok * CCH + col] = acc[i][j] + bias[col] + addsrc[tok * CCH + col];
            }
        } else if (EPI == 2) {
#pragma unroll
            for (int j = 0; j < 8; j++) {
                const int col = bn + tx * 8 + j;
                if (col < N) {
                    const float vv = acc[i][j] + bias[col];
                    C0[(size_t)row * N + col] =
                        0.5f * vv * (1.0f + erff(vv * 0.70710678118654752440f));
                }
            }
        } else {  // EPI == 3
#pragma unroll
            for (int j = 0; j < 8; j++) {
                const int col = bn + tx * 8 + j;
                if (col < N)
                    C0[(size_t)row * N + col] =
                        acc[i][j] + bias[col] + addsrc[(size_t)row * N + col];
            }
        }
    }
}

// ---------------- windowed attention: one block per (window, head) ------------
__global__ __launch_bounds__(256)
void attn_kernel(const float* __restrict__ q, const float* __restrict__ k,
                 const float* __restrict__ v, const float* __restrict__ rpb,
                 float* __restrict__ out)
{
    __shared__ float qs[NN * HD];
    __shared__ float ks[NN * HD];
    __shared__ float vs[NN * HD];
    __shared__ float S[NN * 50];

    const int win  = blockIdx.x;
    const int head = blockIdx.y;
    const int tid  = threadIdx.x;

    const size_t base = (size_t)(win * NHEAD + head) * NN * HD;
    const float4* q4 = (const float4*)(q + base);
    const float4* k4 = (const float4*)(k + base);
    const float4* v4 = (const float4*)(v + base);
    for (int i = tid; i < NN * HD / 4; i += 256) {
        ((float4*)qs)[i] = q4[i];
        ((float4*)ks)[i] = k4[i];
        ((float4*)vs)[i] = v4[i];
    }
    __syncthreads();

    const int wl = win & 63;
    const int wh = wl >> 3, ww = wl & 7;

    // S = q@k^T (q pre-scaled) + rel-pos bias + shift mask
    for (int e = tid; e < NN * NN; e += 256) {
        const int i = e / NN;
        const int j = e - i * NN;
        float s = 0.f;
#pragma unroll
        for (int d = 0; d < HD; d += 4) {
            const float4 a  = *(const float4*)&qs[i * HD + d];
            const float4 bq = *(const float4*)&ks[j * HD + d];
            s += a.x * bq.x + a.y * bq.y + a.z * bq.z + a.w * bq.w;
        }
        const int ih = i / 7, iw = i - ih * 7;
        const int jh = j / 7, jw = j - jh * 7;
        s += rpb[((ih - jh + 6) * 13 + (iw - jw + 6)) * NHEAD + head];

        const int gih = wh * 7 + ih, giw = ww * 7 + iw;
        const int gjh = wh * 7 + jh, gjw = ww * 7 + jw;
        const int ri = (gih < 49 ? 0 : (gih < 53 ? 1 : 2)) * 3 + (giw < 49 ? 0 : (giw < 53 ? 1 : 2));
        const int rj = (gjh < 49 ? 0 : (gjh < 53 ? 1 : 2)) * 3 + (gjw < 49 ? 0 : (gjw < 53 ? 1 : 2));
        if (ri != rj) s -= 100.0f;
        S[i * 50 + j] = s;
    }
    __syncthreads();

    // row softmax (49 rows, one thread each — work is trivial)
    if (tid < NN) {
        float mx = -1e30f;
        for (int j = 0; j < NN; j++) mx = fmaxf(mx, S[tid * 50 + j]);
        float sum = 0.f;
        for (int j = 0; j < NN; j++) {
            const float e = __expf(S[tid * 50 + j] - mx);
            S[tid * 50 + j] = e;
            sum += e;
        }
        const float inv = 1.0f / sum;
        for (int j = 0; j < NN; j++) S[tid * 50 + j] *= inv;
    }
    __syncthreads();

    // O = P @ V  -> (win*49+i, head*32+d) in the (100352,192) proj-input layout
    for (int e = tid; e < NN * HD; e += 256) {
        const int i = e >> 5;
        const int d = e & 31;
        float o = 0.f;
        for (int j = 0; j < NN; j++) o += S[i * 50 + j] * vs[j * HD + d];
        out[(size_t)(win * NN + i) * CCH + head * HD + d] = o;
    }
}

// ---------------- launch ----------------
extern "C" void kernel_launch(void* const* d_in, const int* in_sizes, int n_in,
                              void* d_out, int out_size)
{
    const float* x      = (const float*)d_in[0];
    const float* n1g    = (const float*)d_in[1];
    const float* n1b    = (const float*)d_in[2];
    const float* qkv_w  = (const float*)d_in[3];
    const float* qkv_b  = (const float*)d_in[4];
    const float* rpb    = (const float*)d_in[5];
    const float* proj_w = (const float*)d_in[6];
    const float* proj_b = (const float*)d_in[7];
    const float* n2g    = (const float*)d_in[8];
    const float* n2b    = (const float*)d_in[9];
    const float* fc1_w  = (const float*)d_in[10];
    const float* fc1_b  = (const float*)d_in[11];
    const float* fc2_w  = (const float*)d_in[12];
    const float* fc2_b  = (const float*)d_in[13];
    float* out = (float*)d_out;

    float *hwin, *q, *k, *v, *ao, *x1, *ln2, *fc1;
    cudaGetSymbolAddress((void**)&hwin, g_hwin);
    cudaGetSymbolAddress((void**)&q,    g_q);
    cudaGetSymbolAddress((void**)&k,    g_k);
    cudaGetSymbolAddress((void**)&v,    g_v);
    cudaGetSymbolAddress((void**)&ao,   g_attnout);
    cudaGetSymbolAddress((void**)&x1,   g_x1);
    cudaGetSymbolAddress((void**)&ln2,  g_ln2);
    cudaGetSymbolAddress((void**)&fc1,  g_fc1);

    // 1) LN1 + cyclic shift + window partition
    ln_kernel<1><<<NTOK / 8, 256>>>(x, n1g, n1b, hwin);

    // 2) QKV GEMM (100352 x 576 x 192), split/scale epilogue
    gemm_k<0><<<dim3(5, NTOK / 128), 256>>>(hwin, qkv_w, qkv_b, nullptr,
                                            q, k, v, NTOK, 3 * CCH, CCH);

    // 3) windowed attention with rel-pos bias + shift mask
    attn_kernel<<<dim3(NWIN, NHEAD), 256>>>(q, k, v, rpb, ao);

    // 4) proj GEMM + window reverse + unshift + residual
    gemm_k<1><<<dim3(2, NTOK / 128), 256>>>(ao, proj_w, proj_b, x,
                                            x1, nullptr, nullptr, NTOK, CCH, CCH);

    // 5) LN2
    ln_kernel<0><<<NTOK / 8, 256>>>(x1, n2g, n2b, ln2);

    // 6) fc1 GEMM + exact GELU
    gemm_k<2><<<dim3(6, NTOK / 128), 256>>>(ln2, fc1_w, fc1_b, nullptr,
                                            fc1, nullptr, nullptr, NTOK, FFDIM, CCH);

    // 7) fc2 GEMM + residual -> output
    gemm_k<3><<<dim3(2, NTOK / 128), 256>>>(fc1, fc2_w, fc2_b, x1,
                                            out, nullptr, nullptr, NTOK, CCH, FFDIM);
}

// round 15
// speedup vs baseline: 1.7926x; 1.7926x over previous
#include <cuda_runtime.h>
#include <math.h>

// ---------------- problem constants ----------------
#define BB      32
#define HH      56
#define CCH     192
#define WS      7
#define SSHIFT  3
#define NHEAD   6
#define HD      32
#define NN      49                  // WS*WS
#define NWIMG   64                  // (56/7)^2
#define NWIN    (BB*NWIMG)          // 2048
#define NTOK    (BB*HH*HH)          // 100352
#define FFDIM   768                 // 4*C
#define QK_SCALE 0.1767766952966369f  // 32^-0.5

// ---------------- scratch (device globals; no allocs allowed) ----------------
__device__ float g_hwin[(size_t)NTOK * CCH];
__device__ float g_q[(size_t)NTOK * CCH];
__device__ float g_k[(size_t)NTOK * CCH];
__device__ float g_v[(size_t)NTOK * CCH];
__device__ float g_attnout[(size_t)NTOK * CCH];
__device__ float g_x1[(size_t)NTOK * CCH];
__device__ float g_ln2[(size_t)NTOK * CCH];
__device__ float g_fc1[(size_t)NTOK * FFDIM];

// ---------------- LayerNorm (warp per token), optional shift+window scatter ----
template <int PERM>
__global__ void ln_kernel(const float* __restrict__ x,
                          const float* __restrict__ g,
                          const float* __restrict__ b,
                          float* __restrict__ out)
{
    const int warp = threadIdx.x >> 5;
    const int lane = threadIdx.x & 31;
    const int tok  = blockIdx.x * 8 + warp;   // grid = NTOK/8 exactly

    const float* px = x + (size_t)tok * CCH;
    float v[6];
    float s = 0.f, sq = 0.f;
#pragma unroll
    for (int t = 0; t < 6; t++) {
        float a = px[lane + 32 * t];
        v[t] = a; s += a; sq += a * a;
    }
#pragma unroll
    for (int o = 16; o > 0; o >>= 1) {
        s  += __shfl_xor_sync(0xffffffffu, s,  o);
        sq += __shfl_xor_sync(0xffffffffu, sq, o);
    }
    const float mu  = s * (1.0f / CCH);
    const float var = sq * (1.0f / CCH) - mu * mu;
    const float inv = rsqrtf(var + 1e-5f);

    size_t drow;
    if (PERM) {
        const int bb = tok / (HH * HH);
        const int hw = tok - bb * (HH * HH);
        const int h  = hw / HH, w = hw - (hw / HH) * HH;
        int ph = h - SSHIFT; if (ph < 0) ph += HH;
        int pw = w - SSHIFT; if (pw < 0) pw += HH;
        const int wh = ph / WS, r = ph - wh * WS;
        const int ww = pw / WS, c = pw - ww * WS;
        drow = (size_t)((bb * NWIMG + wh * 8 + ww) * NN + r * WS + c);
    } else {
        drow = (size_t)tok;
    }
    float* po = out + drow * CCH;
#pragma unroll
    for (int t = 0; t < 6; t++) {
        const int ch = lane + 32 * t;
        po[ch] = (v[t] - mu) * inv * g[ch] + b[ch];
    }
}

// ---------------- fp32 -> tf32 conversion ----------------
__device__ __forceinline__ float f2tf(float f) {
    unsigned u;
    asm("cvt.rna.tf32.f32 %0, %1;" : "=r"(u) : "f"(f));
    return __uint_as_float(u);
}

// ---------------- tensor-core GEMM (tf32 mma.sync m16n8k8) --------------------
// CTA tile 128x64, BK=16, 256 threads = 8 warps (4m x 2n), warp tile 32x32.
// A: (M,K) row-major fp32.  B: (K,N) row-major fp32.
// Requires: M%128==0, N%64==0, K%16==0  (all shapes here satisfy this).
// EPI 0: qkv split/scale   -> C0=q (pre-scaled), C1=k, C2=v   (win,head,n,hd)
// EPI 1: proj + residual, window-reverse+unshift scatter       -> C0=x1 (+addsrc=x)
// EPI 2: bias + exact GELU                                     -> C0=fc1out
// EPI 3: bias + residual add                                   -> C0=out (+addsrc=x1)
#define A_STRIDE 20   // 16 + 4 pad: banks (h*20 + j) % 32 all distinct
#define B_STRIDE 72   // 64 + 8 pad: banks (j*8 + h) % 32 all distinct

template <int EPI>
__global__ __launch_bounds__(256)
void gemm_tc(const float* __restrict__ A, const float* __restrict__ B,
             const float* __restrict__ bias, const float* __restrict__ addsrc,
             float* __restrict__ C0, float* __restrict__ C1, float* __restrict__ C2,
             int M, int N, int K)
{
    __shared__ float As[2][128 * A_STRIDE];
    __shared__ float Bs[2][16 * B_STRIDE];

    const int tid  = threadIdx.x;
    const int lane = tid & 31;
    const int w    = tid >> 5;
    const int wm   = w >> 1;          // 0..3
    const int wn   = w & 1;           // 0..1
    const int bm   = blockIdx.y * 128;
    const int bn   = blockIdx.x * 64;

    // global load assignments
    const int aRow = tid >> 1;                 // 0..127
    const int aK   = (tid & 1) * 8;            // 0 or 8
    const int bRow = tid >> 4;                 // 0..15
    const int bC   = (tid & 15) * 4;           // 0..60
    const float* Ag = A + (size_t)(bm + aRow) * K + aK;
    const float* Bg = B + (size_t)bRow * N + bn + bC;

    float acc[2][4][4];
#pragma unroll
    for (int mi = 0; mi < 2; mi++)
#pragma unroll
        for (int ni = 0; ni < 4; ni++)
#pragma unroll
            for (int r = 0; r < 4; r++) acc[mi][ni][r] = 0.f;

    const int T = K >> 4;

    float4 pa0 = *(const float4*)(Ag);
    float4 pa1 = *(const float4*)(Ag + 4);
    float4 pb  = *(const float4*)(Bg);
    {
        float* as = &As[0][aRow * A_STRIDE + aK];
        as[0] = f2tf(pa0.x); as[1] = f2tf(pa0.y); as[2] = f2tf(pa0.z); as[3] = f2tf(pa0.w);
        as[4] = f2tf(pa1.x); as[5] = f2tf(pa1.y); as[6] = f2tf(pa1.z); as[7] = f2tf(pa1.w);
        float* bsp = &Bs[0][bRow * B_STRIDE + bC];
        bsp[0] = f2tf(pb.x); bsp[1] = f2tf(pb.y); bsp[2] = f2tf(pb.z); bsp[3] = f2tf(pb.w);
    }
    __syncthreads();

    for (int t = 0; t < T; t++) {
        if (t + 1 < T) {
            const float* Ag2 = Ag + (t + 1) * 16;
            pa0 = *(const float4*)(Ag2);
            pa1 = *(const float4*)(Ag2 + 4);
            pb  = *(const float4*)(Bg + (size_t)(t + 1) * 16 * N);
        }
        const float* as = As[t & 1];
        const float* bs = Bs[t & 1];
#pragma unroll
        for (int kc = 0; kc < 2; kc++) {
            const int k8 = kc * 8;
            unsigned af[2][4], bf[4][2];
#pragma unroll
            for (int mi = 0; mi < 2; mi++) {
                const int r0 = wm * 32 + mi * 16 + (lane >> 2);
                const int cc = k8 + (lane & 3);
                af[mi][0] = __float_as_uint(as[r0 * A_STRIDE + cc]);
                af[mi][1] = __float_as_uint(as[(r0 + 8) * A_STRIDE + cc]);
                af[mi][2] = __float_as_uint(as[r0 * A_STRIDE + cc + 4]);
                af[mi][3] = __float_as_uint(as[(r0 + 8) * A_STRIDE + cc + 4]);
            }
#pragma unroll
            for (int ni = 0; ni < 4; ni++) {
                const int col = wn * 32 + ni * 8 + (lane >> 2);
                const int kr  = k8 + (lane & 3);
                bf[ni][0] = __float_as_uint(bs[kr * B_STRIDE + col]);
                bf[ni][1] = __float_as_uint(bs[(kr + 4) * B_STRIDE + col]);
            }
#pragma unroll
            for (int mi = 0; mi < 2; mi++)
#pragma unroll
                for (int ni = 0; ni < 4; ni++) {
                    float* c = acc[mi][ni];
                    asm volatile(
                        "mma.sync.aligned.m16n8k8.row.col.f32.tf32.tf32.f32 "
                        "{%0,%1,%2,%3}, {%4,%5,%6,%7}, {%8,%9}, {%0,%1,%2,%3};"
                        : "+f"(c[0]), "+f"(c[1]), "+f"(c[2]), "+f"(c[3])
                        : "r"(af[mi][0]), "r"(af[mi][1]), "r"(af[mi][2]), "r"(af[mi][3]),
                          "r"(bf[ni][0]), "r"(bf[ni][1]));
                }
        }
        if (t + 1 < T) {
            float* as2 = &As[(t + 1) & 1][aRow * A_STRIDE + aK];
            as2[0] = f2tf(pa0.x); as2[1] = f2tf(pa0.y); as2[2] = f2tf(pa0.z); as2[3] = f2tf(pa0.w);
            as2[4] = f2tf(pa1.x); as2[5] = f2tf(pa1.y); as2[6] = f2tf(pa1.z); as2[7] = f2tf(pa1.w);
            float* bs2 = &Bs[(t + 1) & 1][bRow * B_STRIDE + bC];
            bs2[0] = f2tf(pb.x); bs2[1] = f2tf(pb.y); bs2[2] = f2tf(pb.z); bs2[3] = f2tf(pb.w);
            __syncthreads();
        }
    }

    // ---------------- epilogue ----------------
    // acc regs: c0=(row,col) c1=(row,col+1) c2=(row+8,col) c3=(row+8,col+1)
#pragma unroll
    for (int mi = 0; mi < 2; mi++) {
#pragma unroll
        for (int half = 0; half < 2; half++) {
            const int row = bm + wm * 32 + mi * 16 + (lane >> 2) + half * 8;

            if (EPI == 0) {
                const int win = row / NN;
                const int n   = row - win * NN;
#pragma unroll
                for (int ni = 0; ni < 4; ni++) {
                    const int col = bn + wn * 32 + ni * 8 + (lane & 3) * 2;
                    float v0 = acc[mi][ni][half * 2 + 0] + bias[col];
                    float v1 = acc[mi][ni][half * 2 + 1] + bias[col + 1];
                    const int part = col / CCH;
                    const int rem  = col - part * CCH;
                    const int head = rem >> 5;
                    const int d    = rem & 31;
                    if (part == 0) { v0 *= QK_SCALE; v1 *= QK_SCALE; }
                    float* dst = (part == 0) ? C0 : (part == 1) ? C1 : C2;
                    *(float2*)&dst[(size_t)((win * NHEAD + head) * NN + n) * HD + d] =
                        make_float2(v0, v1);
                }
            } else if (EPI == 1) {
                const int win = row / NN;
                const int n   = row - win * NN;
                const int bb  = win >> 6;
                const int wl  = win & 63;
                const int wh  = wl >> 3, ww = wl & 7;
                const int r   = n / 7,   c  = n - (n / 7) * 7;
                int h = wh * 7 + r + SSHIFT; if (h >= HH) h -= HH;
                int wcol = ww * 7 + c + SSHIFT; if (wcol >= HH) wcol -= HH;
                const size_t tok = (size_t)bb * (HH * HH) + h * HH + wcol;
#pragma unroll
                for (int ni = 0; ni < 4; ni++) {
                    const int col = bn + wn * 32 + ni * 8 + (lane & 3) * 2;
                    const float2 ad = *(const float2*)&addsrc[tok * CCH + col];
                    float v0 = acc[mi][ni][half * 2 + 0] + bias[col] + ad.x;
                    float v1 = acc[mi][ni][half * 2 + 1] + bias[col + 1] + ad.y;
                    *(float2*)&C0[tok * CCH + col] = make_float2(v0, v1);
                }
            } else if (EPI == 2) {
#pragma unroll
                for (int ni = 0; ni < 4; ni++) {
                    const int col = bn + wn * 32 + ni * 8 + (lane & 3) * 2;
                    float v0 = acc[mi][ni][half * 2 + 0] + bias[col];
                    float v1 = acc[mi][ni][half * 2 + 1] + bias[col + 1];
                    v0 = 0.5f * v0 * (1.0f + erff(v0 * 0.70710678118654752440f));
                    v1 = 0.5f * v1 * (1.0f + erff(v1 * 0.70710678118654752440f));
                    *(float2*)&C0[(size_t)row * N + col] = make_float2(v0, v1);
                }
            } else {  // EPI == 3
#pragma unroll
                for (int ni = 0; ni < 4; ni++) {
                    const int col = bn + wn * 32 + ni * 8 + (lane & 3) * 2;
                    const float2 ad = *(const float2*)&addsrc[(size_t)row * N + col];
                    float v0 = acc[mi][ni][half * 2 + 0] + bias[col] + ad.x;
                    float v1 = acc[mi][ni][half * 2 + 1] + bias[col + 1] + ad.y;
                    *(float2*)&C0[(size_t)row * N + col] = make_float2(v0, v1);
                }
            }
        }
    }
}

// ---------------- windowed attention: one block per (window, head) ------------
__global__ __launch_bounds__(256)
void attn_kernel(const float* __restrict__ q, const float* __restrict__ k,
                 const float* __restrict__ v, const float* __restrict__ rpb,
                 float* __restrict__ out)
{
    __shared__ float qs[NN * HD];
    __shared__ float ks[NN * HD];
    __shared__ float vs[NN * HD];
    __shared__ float S[NN * 50];

    const int win  = blockIdx.x;
    const int head = blockIdx.y;
    const int tid  = threadIdx.x;

    const size_t base = (size_t)(win * NHEAD + head) * NN * HD;
    const float4* q4 = (const float4*)(q + base);
    const float4* k4 = (const float4*)(k + base);
    const float4* v4 = (const float4*)(v + base);
    for (int i = tid; i < NN * HD / 4; i += 256) {
        ((float4*)qs)[i] = q4[i];
        ((float4*)ks)[i] = k4[i];
        ((float4*)vs)[i] = v4[i];
    }
    __syncthreads();

    const int wl = win & 63;
    const int wh = wl >> 3, ww = wl & 7;

    for (int e = tid; e < NN * NN; e += 256) {
        const int i = e / NN;
        const int j = e - i * NN;
        float s = 0.f;
#pragma unroll
        for (int d = 0; d < HD; d += 4) {
            const float4 a  = *(const float4*)&qs[i * HD + d];
            const float4 bq = *(const float4*)&ks[j * HD + d];
            s += a.x * bq.x + a.y * bq.y + a.z * bq.z + a.w * bq.w;
        }
        const int ih = i / 7, iw = i - ih * 7;
        const int jh = j / 7, jw = j - jh * 7;
        s += rpb[((ih - jh + 6) * 13 + (iw - jw + 6)) * NHEAD + head];

        const int gih = wh * 7 + ih, giw = ww * 7 + iw;
        const int gjh = wh * 7 + jh, gjw = ww * 7 + jw;
        const int ri = (gih < 49 ? 0 : (gih < 53 ? 1 : 2)) * 3 + (giw < 49 ? 0 : (giw < 53 ? 1 : 2));
        const int rj = (gjh < 49 ? 0 : (gjh < 53 ? 1 : 2)) * 3 + (gjw < 49 ? 0 : (gjw < 53 ? 1 : 2));
        if (ri != rj) s -= 100.0f;
        S[i * 50 + j] = s;
    }
    __syncthreads();

    if (tid < NN) {
        float mx = -1e30f;
        for (int j = 0; j < NN; j++) mx = fmaxf(mx, S[tid * 50 + j]);
        float sum = 0.f;
        for (int j = 0; j < NN; j++) {
            const float e = __expf(S[tid * 50 + j] - mx);
            S[tid * 50 + j] = e;
            sum += e;
        }
        const float inv = 1.0f / sum;
        for (int j = 0; j < NN; j++) S[tid * 50 + j] *= inv;
    }
    __syncthreads();

    for (int e = tid; e < NN * HD; e += 256) {
        const int i = e >> 5;
        const int d = e & 31;
        float o = 0.f;
        for (int j = 0; j < NN; j++) o += S[i * 50 + j] * vs[j * HD + d];
        out[(size_t)(win * NN + i) * CCH + head * HD + d] = o;
    }
}

// ---------------- launch ----------------
extern "C" void kernel_launch(void* const* d_in, const int* in_sizes, int n_in,
                              void* d_out, int out_size)
{
    const float* x      = (const float*)d_in[0];
    const float* n1g    = (const float*)d_in[1];
    const float* n1b    = (const float*)d_in[2];
    const float* qkv_w  = (const float*)d_in[3];
    const float* qkv_b  = (const float*)d_in[4];
    const float* rpb    = (const float*)d_in[5];
    const float* proj_w = (const float*)d_in[6];
    const float* proj_b = (const float*)d_in[7];
    const float* n2g    = (const float*)d_in[8];
    const float* n2b    = (const float*)d_in[9];
    const float* fc1_w  = (const float*)d_in[10];
    const float* fc1_b  = (const float*)d_in[11];
    const float* fc2_w  = (const float*)d_in[12];
    const float* fc2_b  = (const float*)d_in[13];
    float* out = (float*)d_out;

    float *hwin, *q, *k, *v, *ao, *x1, *ln2, *fc1;
    cudaGetSymbolAddress((void**)&hwin, g_hwin);
    cudaGetSymbolAddress((void**)&q,    g_q);
    cudaGetSymbolAddress((void**)&k,    g_k);
    cudaGetSymbolAddress((void**)&v,    g_v);
    cudaGetSymbolAddress((void**)&ao,   g_attnout);
    cudaGetSymbolAddress((void**)&x1,   g_x1);
    cudaGetSymbolAddress((void**)&ln2,  g_ln2);
    cudaGetSymbolAddress((void**)&fc1,  g_fc1);

    // 1) LN1 + cyclic shift + window partition
    ln_kernel<1><<<NTOK / 8, 256>>>(x, n1g, n1b, hwin);

    // 2) QKV GEMM (100352 x 576 x 192), split/scale epilogue
    gemm_tc<0><<<dim3(576 / 64, NTOK / 128), 256>>>(hwin, qkv_w, qkv_b, nullptr,
                                                    q, k, v, NTOK, 3 * CCH, CCH);

    // 3) windowed attention with rel-pos bias + shift mask
    attn_kernel<<<dim3(NWIN, NHEAD), 256>>>(q, k, v, rpb, ao);

    // 4) proj GEMM + window reverse + unshift + residual
    gemm_tc<1><<<dim3(CCH / 64, NTOK / 128), 256>>>(ao, proj_w, proj_b, x,
                                                    x1, nullptr, nullptr, NTOK, CCH, CCH);

    // 5) LN2
    ln_kernel<0><<<NTOK / 8, 256>>>(x1, n2g, n2b, ln2);

    // 6) fc1 GEMM + exact GELU
    gemm_tc<2><<<dim3(FFDIM / 64, NTOK / 128), 256>>>(ln2, fc1_w, fc1_b, nullptr,
                                                      fc1, nullptr, nullptr, NTOK, FFDIM, CCH);

    // 7) fc2 GEMM + residual -> output
    gemm_tc<3><<<dim3(CCH / 64, NTOK / 128), 256>>>(fc1, fc2_w, fc2_b, x1,
                                                    out, nullptr, nullptr, NTOK, CCH, FFDIM);
}

// round 16
// speedup vs baseline: 2.2670x; 1.2647x over previous
#include <cuda_runtime.h>
#include <cuda_bf16.h>
#include <math.h>

// ---------------- problem constants ----------------
#define BB      32
#define HH      56
#define CCH     192
#define WS      7
#define SSHIFT  3
#define NHEAD   6
#define HD      32
#define NN      49                  // WS*WS
#define NWIMG   64                  // (56/7)^2
#define NWIN    (BB*NWIMG)          // 2048
#define NTOK    (BB*HH*HH)          // 100352
#define FFDIM   768                 // 4*C
#define QK_SCALE 0.1767766952966369f  // 32^-0.5

// ---------------- scratch (device globals; no allocs allowed) ----------------
__device__ __nv_bfloat16 g_hwin[(size_t)NTOK * CCH];
__device__ float         g_q[(size_t)NTOK * CCH];
__device__ float         g_k[(size_t)NTOK * CCH];
__device__ float         g_v[(size_t)NTOK * CCH];
__device__ __nv_bfloat16 g_ao[(size_t)NTOK * CCH];
__device__ float         g_x1[(size_t)NTOK * CCH];
__device__ __nv_bfloat16 g_ln2[(size_t)NTOK * CCH];
__device__ __nv_bfloat16 g_fc1[(size_t)NTOK * FFDIM];
// bf16 transposed weights (N,K)
__device__ __nv_bfloat16 g_wqkv[(size_t)3 * CCH * CCH];
__device__ __nv_bfloat16 g_wproj[(size_t)CCH * CCH];
__device__ __nv_bfloat16 g_wfc1[(size_t)CCH * FFDIM];
__device__ __nv_bfloat16 g_wfc2[(size_t)FFDIM * CCH];

// ---------------- weight convert + transpose: fp32 (K,N) -> bf16 (N,K) --------
__global__ void wtrans(const float* __restrict__ w, __nv_bfloat16* __restrict__ wt,
                       int K, int N)
{
    const int idx = blockIdx.x * 256 + threadIdx.x;
    if (idx < K * N) {
        const int k = idx / N, n = idx - k * N;
        wt[(size_t)n * K + k] = __float2bfloat16(w[idx]);
    }
}

// ---------------- LayerNorm (warp per token) -> bf16, optional shift+window ----
template <int PERM>
__global__ void ln_kernel(const float* __restrict__ x,
                          const float* __restrict__ g,
                          const float* __restrict__ b,
                          __nv_bfloat16* __restrict__ out)
{
    const int warp = threadIdx.x >> 5;
    const int lane = threadIdx.x & 31;
    const int tok  = blockIdx.x * 8 + warp;   // grid = NTOK/8 exactly

    const float* px = x + (size_t)tok * CCH;
    float2 v[3];
    float s = 0.f, sq = 0.f;
#pragma unroll
    for (int t = 0; t < 3; t++) {
        float2 a = *(const float2*)&px[2 * lane + 64 * t];
        v[t] = a;
        s += a.x + a.y; sq += a.x * a.x + a.y * a.y;
    }
#pragma unroll
    for (int o = 16; o > 0; o >>= 1) {
        s  += __shfl_xor_sync(0xffffffffu, s,  o);
        sq += __shfl_xor_sync(0xffffffffu, sq, o);
    }
    const float mu  = s * (1.0f / CCH);
    const float var = sq * (1.0f / CCH) - mu * mu;
    const float inv = rsqrtf(var + 1e-5f);

    size_t drow;
    if (PERM) {
        const int bb = tok / (HH * HH);
        const int hw = tok - bb * (HH * HH);
        const int h  = hw / HH, w = hw - (hw / HH) * HH;
        int ph = h - SSHIFT; if (ph < 0) ph += HH;
        int pw = w - SSHIFT; if (pw < 0) pw += HH;
        const int wh = ph / WS, r = ph - wh * WS;
        const int ww = pw / WS, c = pw - ww * WS;
        drow = (size_t)((bb * NWIMG + wh * 8 + ww) * NN + r * WS + c);
    } else {
        drow = (size_t)tok;
    }
    __nv_bfloat162* po = (__nv_bfloat162*)(out + drow * CCH);
#pragma unroll
    for (int t = 0; t < 3; t++) {
        const int ch = 2 * lane + 64 * t;
        float2 o2;
        o2.x = (v[t].x - mu) * inv * g[ch] + b[ch];
        o2.y = (v[t].y - mu) * inv * g[ch + 1] + b[ch + 1];
        po[lane + 32 * t] = __float22bfloat162_rn(o2);
    }
}

// ---------------- tensor-core GEMM (bf16 mma.sync m16n8k16) -------------------
// CTA tile 128x64, BK=32, 256 threads = 8 warps (4m x 2n), warp tile 32x32.
// A: (M,K) row-major bf16.  B: (N,K) row-major bf16 (pre-transposed weights).
// Requires: M%128==0, N%64==0, K%32==0  (all shapes here satisfy this).
// EPI 0: qkv split/scale (fp32 out)    -> C0=q, C1=k, C2=v  (win,head,n,hd)
// EPI 1: proj+residual, reverse+unshift-> C0=x1 fp32 (+addsrc=x)
// EPI 2: bias + exact GELU             -> C0=fc1out bf16
// EPI 3: bias + residual add           -> C0=out fp32 (+addsrc=x1)
#define ASW 20   // uint32 words per A smem row (16 + 4 pad) -> conflict-free frags
#define BSW 20   // uint32 words per B smem row

template <int EPI>
__global__ __launch_bounds__(256)
void gemm_bf(const __nv_bfloat16* __restrict__ A, const __nv_bfloat16* __restrict__ B,
             const float* __restrict__ bias, const float* __restrict__ addsrc,
             void* __restrict__ C0v, float* __restrict__ C1, float* __restrict__ C2,
             int M, int N, int K)
{
    __shared__ __align__(16) unsigned As[2][128 * ASW];
    __shared__ __align__(16) unsigned Bs[2][64 * BSW];

    const int tid  = threadIdx.x;
    const int lane = tid & 31;
    const int w    = tid >> 5;
    const int wm   = w >> 1;          // 0..3
    const int wn   = w & 1;           // 0..1
    const int bm   = blockIdx.y * 128;
    const int bn   = blockIdx.x * 64;

    // global load assignments (bf16, 8 elems per uint4)
    const int aRow = tid >> 1;                  // 0..127
    const int aK   = (tid & 1) * 16;            // 0 or 16 (bf16 elems)
    const int bRow = tid >> 2;                  // 0..63 (N col)
    const int bK   = (tid & 3) * 8;              // 0..24
    const __nv_bfloat16* Ag = A + (size_t)(bm + aRow) * K + aK;
    const __nv_bfloat16* Bg = B + (size_t)(bn + bRow) * K + bK;

    const int aSoff = aRow * ASW + (tid & 1) * 8;   // word offset
    const int bSoff = bRow * BSW + (tid & 3) * 4;

    float acc[2][4][4];
#pragma unroll
    for (int mi = 0; mi < 2; mi++)
#pragma unroll
        for (int ni = 0; ni < 4; ni++)
#pragma unroll
            for (int r = 0; r < 4; r++) acc[mi][ni][r] = 0.f;

    const int T = K >> 5;

    uint4 pa0 = *(const uint4*)(Ag);
    uint4 pa1 = *(const uint4*)(Ag + 8);
    uint4 pb  = *(const uint4*)(Bg);
    *(uint4*)&As[0][aSoff]     = pa0;
    *(uint4*)&As[0][aSoff + 4] = pa1;
    *(uint4*)&Bs[0][bSoff]     = pb;
    __syncthreads();

    for (int t = 0; t < T; t++) {
        if (t + 1 < T) {
            const __nv_bfloat16* Ag2 = Ag + (t + 1) * 32;
            const __nv_bfloat16* Bg2 = Bg + (t + 1) * 32;
            pa0 = *(const uint4*)(Ag2);
            pa1 = *(const uint4*)(Ag2 + 8);
            pb  = *(const uint4*)(Bg2);
        }
        const unsigned* as = As[t & 1];
        const unsigned* bs = Bs[t & 1];
#pragma unroll
        for (int kc = 0; kc < 2; kc++) {
            const int kb = kc * 8;               // word base for this k16 chunk
            unsigned af[2][4], bf[4][2];
#pragma unroll
            for (int mi = 0; mi < 2; mi++) {
                const int r0 = wm * 32 + mi * 16 + (lane >> 2);
                const int cw = kb + (lane & 3);
                af[mi][0] = as[r0 * ASW + cw];
                af[mi][1] = as[(r0 + 8) * ASW + cw];
                af[mi][2] = as[r0 * ASW + cw + 4];
                af[mi][3] = as[(r0 + 8) * ASW + cw + 4];
            }
#pragma unroll
            for (int ni = 0; ni < 4; ni++) {
                const int col = wn * 32 + ni * 8 + (lane >> 2);
                const int cw  = kb + (lane & 3);
                bf[ni][0] = bs[col * BSW + cw];
                bf[ni][1] = bs[col * BSW + cw + 4];
            }
#pragma unroll
            for (int mi = 0; mi < 2; mi++)
#pragma unroll
                for (int ni = 0; ni < 4; ni++) {
                    float* c = acc[mi][ni];
                    asm volatile(
                        "mma.sync.aligned.m16n8k16.row.col.f32.bf16.bf16.f32 "
                        "{%0,%1,%2,%3}, {%4,%5,%6,%7}, {%8,%9}, {%0,%1,%2,%3};"
                        : "+f"(c[0]), "+f"(c[1]), "+f"(c[2]), "+f"(c[3])
                        : "r"(af[mi][0]), "r"(af[mi][1]), "r"(af[mi][2]), "r"(af[mi][3]),
                          "r"(bf[ni][0]), "r"(bf[ni][1]));
                }
        }
        if (t + 1 < T) {
            const int nb = (t + 1) & 1;
            *(uint4*)&As[nb][aSoff]     = pa0;
            *(uint4*)&As[nb][aSoff + 4] = pa1;
            *(uint4*)&Bs[nb][bSoff]     = pb;
            __syncthreads();
        }
    }

    // ---------------- epilogue ----------------
    // acc regs: c0=(row,col) c1=(row,col+1) c2=(row+8,col) c3=(row+8,col+1)
#pragma unroll
    for (int mi = 0; mi < 2; mi++) {
#pragma unroll
        for (int half = 0; half < 2; half++) {
            const int row = bm + wm * 32 + mi * 16 + (lane >> 2) + half * 8;

            if (EPI == 0) {
                const int win = row / NN;
                const int n   = row - win * NN;
#pragma unroll
                for (int ni = 0; ni < 4; ni++) {
                    const int col = bn + wn * 32 + ni * 8 + (lane & 3) * 2;
                    float v0 = acc[mi][ni][half * 2 + 0] + bias[col];
                    float v1 = acc[mi][ni][half * 2 + 1] + bias[col + 1];
                    const int part = col / CCH;
                    const int rem  = col - part * CCH;
                    const int head = rem >> 5;
                    const int d    = rem & 31;
                    if (part == 0) { v0 *= QK_SCALE; v1 *= QK_SCALE; }
                    float* dst = (part == 0) ? (float*)C0v : (part == 1) ? C1 : C2;
                    *(float2*)&dst[(size_t)((win * NHEAD + head) * NN + n) * HD + d] =
                        make_float2(v0, v1);
                }
            } else if (EPI == 1) {
                const int win = row / NN;
                const int n   = row - win * NN;
                const int bb  = win >> 6;
                const int wl  = win & 63;
                const int wh  = wl >> 3, ww = wl & 7;
                const int r   = n / 7,   c  = n - (n / 7) * 7;
                int h = wh * 7 + r + SSHIFT; if (h >= HH) h -= HH;
                int wcol = ww * 7 + c + SSHIFT; if (wcol >= HH) wcol -= HH;
                const size_t tok = (size_t)bb * (HH * HH) + h * HH + wcol;
#pragma unroll
                for (int ni = 0; ni < 4; ni++) {
                    const int col = bn + wn * 32 + ni * 8 + (lane & 3) * 2;
                    const float2 ad = *(const float2*)&addsrc[tok * CCH + col];
                    float v0 = acc[mi][ni][half * 2 + 0] + bias[col] + ad.x;
                    float v1 = acc[mi][ni][half * 2 + 1] + bias[col + 1] + ad.y;
                    *(float2*)&((float*)C0v)[tok * CCH + col] = make_float2(v0, v1);
                }
            } else if (EPI == 2) {
#pragma unroll
                for (int ni = 0; ni < 4; ni++) {
                    const int col = bn + wn * 32 + ni * 8 + (lane & 3) * 2;
                    float v0 = acc[mi][ni][half * 2 + 0] + bias[col];
                    float v1 = acc[mi][ni][half * 2 + 1] + bias[col + 1];
                    v0 = 0.5f * v0 * (1.0f + erff(v0 * 0.70710678118654752440f));
                    v1 = 0.5f * v1 * (1.0f + erff(v1 * 0.70710678118654752440f));
                    ((__nv_bfloat162*)C0v)[((size_t)row * N + col) >> 1] =
                        __float22bfloat162_rn(make_float2(v0, v1));
                }
            } else {  // EPI == 3
#pragma unroll
                for (int ni = 0; ni < 4; ni++) {
                    const int col = bn + wn * 32 + ni * 8 + (lane & 3) * 2;
                    const float2 ad = *(const float2*)&addsrc[(size_t)row * N + col];
                    float v0 = acc[mi][ni][half * 2 + 0] + bias[col] + ad.x;
                    float v1 = acc[mi][ni][half * 2 + 1] + bias[col + 1] + ad.y;
                    *(float2*)&((float*)C0v)[(size_t)row * N + col] = make_float2(v0, v1);
                }
            }
        }
    }
}

// ---------------- windowed attention: one block per (window, head) ------------
__global__ __launch_bounds__(256)
void attn_kernel(const float* __restrict__ q, const float* __restrict__ k,
                 const float* __restrict__ v, const float* __restrict__ rpb,
                 __nv_bfloat16* __restrict__ out)
{
    __shared__ float qs[NN * HD];
    __shared__ float ks[NN * HD];
    __shared__ float vs[NN * HD];
    __shared__ float S[NN * 50];

    const int win  = blockIdx.x;
    const int head = blockIdx.y;
    const int tid  = threadIdx.x;

    const size_t base = (size_t)(win * NHEAD + head) * NN * HD;
    const float4* q4 = (const float4*)(q + base);
    const float4* k4 = (const float4*)(k + base);
    const float4* v4 = (const float4*)(v + base);
    for (int i = tid; i < NN * HD / 4; i += 256) {
        ((float4*)qs)[i] = q4[i];
        ((float4*)ks)[i] = k4[i];
        ((float4*)vs)[i] = v4[i];
    }
    __syncthreads();

    const int wl = win & 63;
    const int wh = wl >> 3, ww = wl & 7;

    for (int e = tid; e < NN * NN; e += 256) {
        const int i = e / NN;
        const int j = e - i * NN;
        float s = 0.f;
#pragma unroll
        for (int d = 0; d < HD; d += 4) {
            const float4 a  = *(const float4*)&qs[i * HD + d];
            const float4 bq = *(const float4*)&ks[j * HD + d];
            s += a.x * bq.x + a.y * bq.y + a.z * bq.z + a.w * bq.w;
        }
        const int ih = i / 7, iw = i - ih * 7;
        const int jh = j / 7, jw = j - jh * 7;
        s += rpb[((ih - jh + 6) * 13 + (iw - jw + 6)) * NHEAD + head];

        const int gih = wh * 7 + ih, giw = ww * 7 + iw;
        const int gjh = wh * 7 + jh, gjw = ww * 7 + jw;
        const int ri = (gih < 49 ? 0 : (gih < 53 ? 1 : 2)) * 3 + (giw < 49 ? 0 : (giw < 53 ? 1 : 2));
        const int rj = (gjh < 49 ? 0 : (gjh < 53 ? 1 : 2)) * 3 + (gjw < 49 ? 0 : (gjw < 53 ? 1 : 2));
        if (ri != rj) s -= 100.0f;
        S[i * 50 + j] = s;
    }
    __syncthreads();

    if (tid < NN) {
        float mx = -1e30f;
        for (int j = 0; j < NN; j++) mx = fmaxf(mx, S[tid * 50 + j]);
        float sum = 0.f;
        for (int j = 0; j < NN; j++) {
            const float e = __expf(S[tid * 50 + j] - mx);
            S[tid * 50 + j] = e;
            sum += e;
        }
        const float inv = 1.0f / sum;
        for (int j = 0; j < NN; j++) S[tid * 50 + j] *= inv;
    }
    __syncthreads();

    for (int e = tid; e < NN * HD; e += 256) {
        const int i = e >> 5;
        const int d = e & 31;
        float o = 0.f;
        for (int j = 0; j < NN; j++) o += S[i * 50 + j] * vs[j * HD + d];
        out[(size_t)(win * NN + i) * CCH + head * HD + d] = __float2bfloat16(o);
    }
}

// ---------------- launch ----------------
extern "C" void kernel_launch(void* const* d_in, const int* in_sizes, int n_in,
                              void* d_out, int out_size)
{
    const float* x      = (const float*)d_in[0];
    const float* n1g    = (const float*)d_in[1];
    const float* n1b    = (const float*)d_in[2];
    const float* qkv_w  = (const float*)d_in[3];
    const float* qkv_b  = (const float*)d_in[4];
    const float* rpb    = (const float*)d_in[5];
    const float* proj_w = (const float*)d_in[6];
    const float* proj_b = (const float*)d_in[7];
    const float* n2g    = (const float*)d_in[8];
    const float* n2b    = (const float*)d_in[9];
    const float* fc1_w  = (const float*)d_in[10];
    const float* fc1_b  = (const float*)d_in[11];
    const float* fc2_w  = (const float*)d_in[12];
    const float* fc2_b  = (const float*)d_in[13];
    float* out = (float*)d_out;

    __nv_bfloat16 *hwin, *ao, *ln2, *fc1, *wqkv, *wproj, *wfc1, *wfc2;
    float *q, *k, *v, *x1;
    cudaGetSymbolAddress((void**)&hwin, g_hwin);
    cudaGetSymbolAddress((void**)&q,    g_q);
    cudaGetSymbolAddress((void**)&k,    g_k);
    cudaGetSymbolAddress((void**)&v,    g_v);
    cudaGetSymbolAddress((void**)&ao,   g_ao);
    cudaGetSymbolAddress((void**)&x1,   g_x1);
    cudaGetSymbolAddress((void**)&ln2,  g_ln2);
    cudaGetSymbolAddress((void**)&fc1,  g_fc1);
    cudaGetSymbolAddress((void**)&wqkv, g_wqkv);
    cudaGetSymbolAddress((void**)&wproj,g_wproj);
    cudaGetSymbolAddress((void**)&wfc1, g_wfc1);
    cudaGetSymbolAddress((void**)&wfc2, g_wfc2);

    // 0) weight convert+transpose to bf16 (N,K)
    wtrans<<<(3 * CCH * CCH + 255) / 256, 256>>>(qkv_w,  wqkv,  CCH, 3 * CCH);
    wtrans<<<(CCH * CCH + 255) / 256, 256>>>(proj_w, wproj, CCH, CCH);
    wtrans<<<(CCH * FFDIM + 255) / 256, 256>>>(fc1_w,  wfc1,  CCH, FFDIM);
    wtrans<<<(FFDIM * CCH + 255) / 256, 256>>>(fc2_w,  wfc2,  FFDIM, CCH);

    // 1) LN1 + cyclic shift + window partition -> bf16
    ln_kernel<1><<<NTOK / 8, 256>>>(x, n1g, n1b, hwin);

    // 2) QKV GEMM (100352 x 576 x 192), split/scale epilogue -> fp32 q,k,v
    gemm_bf<0><<<dim3(576 / 64, NTOK / 128), 256>>>(hwin, wqkv, qkv_b, nullptr,
                                                    q, k, v, NTOK, 3 * CCH, CCH);

    // 3) windowed attention with rel-pos bias + shift mask -> bf16 ao
    attn_kernel<<<dim3(NWIN, NHEAD), 256>>>(q, k, v, rpb, ao);

    // 4) proj GEMM + window reverse + unshift + residual -> fp32 x1
    gemm_bf<1><<<dim3(CCH / 64, NTOK / 128), 256>>>(ao, wproj, proj_b, x,
                                                    x1, nullptr, nullptr, NTOK, CCH, CCH);

    // 5) LN2 -> bf16
    ln_kernel<0><<<NTOK / 8, 256>>>(x1, n2g, n2b, ln2);

    // 6) fc1 GEMM + exact GELU -> bf16
    gemm_bf<2><<<dim3(FFDIM / 64, NTOK / 128), 256>>>(ln2, wfc1, fc1_b, nullptr,
                                                      fc1, nullptr, nullptr, NTOK, FFDIM, CCH);

    // 7) fc2 GEMM + residual -> fp32 output
    gemm_bf<3><<<dim3(CCH / 64, NTOK / 128), 256>>>(fc1, wfc2, fc2_b, x1,
                                                    out, nullptr, nullptr, NTOK, CCH, FFDIM);
}